// round 12
// baseline (speedup 1.0000x reference)
#include <cuda_runtime.h>
#include <cstddef>

// B=4096, T=256, I=6, H=64, gates=3H=192, 2 GRU layers + FC(H->1)
#define T_STEPS 256
#define I_DIM   6
#define HDIM    64
#define G3      192
#define BB      32      // batches per CTA
#define NT      256     // 64 units x 4 batch-groups
#define NBPT    8       // batches per thread
#define PW      68      // weight row pitch (floats): conflict-free LDS.128
#define NCTA    128     // 4096 / 32

typedef unsigned long long u64;

// Packed fp32x2 FMA (SASS FFMA2, PTX-only)
#define FFMA2(acc, a, b) \
    asm("fma.rn.f32x2 %0, %1, %2, %0;" : "+l"(acc) : "l"(a), "l"(b))

union F4U { float4 f; u64 u[2]; };
union F2U { float2 f; u64 u; };

struct SmemLayout {
    float Whh0[G3 * PW];
    float Wih1[G3 * PW];
    float Whh1[G3 * PW];
    float Wih0[G3 * 8];     // pitch 8 (I=6 used) -> float2-aligned pairs
    float bih0[G3];
    float bhh0[G3];
    float bih1[G3];
    float bhh1[G3];
    float h1[2][BB][HDIM];  // ping-pong hidden state, layer 0
    float h2[2][BB][HDIM];  // ping-pong hidden state, layer 1
    float xs[2][BB][8];     // pitch 8 for float2 pairing
    float wfc[HDIM];
    float bfc;
};

__device__ __forceinline__ float sigf(float v) {
    return __fdividef(1.0f, 1.0f + __expf(-v));
}
__device__ __forceinline__ float tanhfast(float v) {
    float c = fminf(fmaxf(v, -15.0f), 15.0f);
    float e = __expf(2.0f * c);
    return __fdividef(e - 1.0f, e + 1.0f);
}
__device__ __forceinline__ float hsum(u64 p) {
    F2U t; t.u = p;
    return t.f.x + t.f.y;
}
__device__ __forceinline__ u64 packbias(float b) {
    F2U t; t.f = make_float2(b, 0.0f);
    return t.u;
}

__global__ __launch_bounds__(NT) void gru_fused_kernel(
    const float* __restrict__ x,
    const float* __restrict__ W_ih0, const float* __restrict__ W_hh0,
    const float* __restrict__ b_ih0, const float* __restrict__ b_hh0,
    const float* __restrict__ W_ih1, const float* __restrict__ W_hh1,
    const float* __restrict__ b_ih1, const float* __restrict__ b_hh1,
    const float* __restrict__ W_fc,  const float* __restrict__ b_fc,
    float* __restrict__ out)
{
    extern __shared__ float smem_raw[];
    SmemLayout& s = *reinterpret_cast<SmemLayout*>(smem_raw);

    const int tid = threadIdx.x;
    const int b0  = blockIdx.x * BB;

    // ---- Stage weights into SMEM ----
    for (int i = tid; i < G3 * HDIM; i += NT) {
        int r = i >> 6, c = i & 63;
        s.Whh0[r * PW + c] = W_hh0[i];
        s.Wih1[r * PW + c] = W_ih1[i];
        s.Whh1[r * PW + c] = W_hh1[i];
    }
    for (int i = tid; i < G3 * 8; i += NT) s.Wih0[i] = 0.0f;   // pad
    for (int i = tid; i < BB * 8 * 2; i += NT) ((float*)s.xs)[i] = 0.0f;
    __syncthreads();
    for (int i = tid; i < G3 * I_DIM; i += NT)
        s.Wih0[(i / I_DIM) * 8 + (i % I_DIM)] = W_ih0[i];
    for (int i = tid; i < G3; i += NT) {
        s.bih0[i] = b_ih0[i];
        s.bhh0[i] = b_hh0[i];
        s.bih1[i] = b_ih1[i];
        s.bhh1[i] = b_hh1[i];
    }
    for (int i = tid; i < BB * HDIM; i += NT) {
        int b = i >> 6, c = i & 63;
        s.h1[0][b][c] = 0.0f;
        s.h2[0][b][c] = 0.0f;
    }
    if (tid < HDIM) s.wfc[tid] = W_fc[tid];
    if (tid == 0)   s.bfc = b_fc[0];

    // x prefetch lanes
    const bool is_pref_lane = (tid < BB * I_DIM);
    const int  lb = is_pref_lane ? (tid / I_DIM) : 0;
    const int  li = is_pref_lane ? (tid % I_DIM) : 0;
    const float* xlane = x + (size_t)(b0 + lb) * T_STEPS * I_DIM + li;
    if (is_pref_lane) s.xs[0][lb][li] = xlane[0];
    __syncthreads();

    // Mapping: gg = hidden unit (0..63); bg = tid>>6 (0..3) -> 8 batches each.
    const int gg  = tid & 63;
    const int bg  = tid >> 6;
    const int bb0 = bg * NBPT;
    const int gr = gg, gz = gg + 64, gn = gg + 128;

    const float* Whh0r = &s.Whh0[gr * PW];
    const float* Whh0z = &s.Whh0[gz * PW];
    const float* Whh0n = &s.Whh0[gn * PW];
    const float* Wih1r = &s.Wih1[gr * PW];
    const float* Wih1z = &s.Wih1[gz * PW];
    const float* Wih1n = &s.Wih1[gn * PW];
    const float* Whh1r = &s.Whh1[gr * PW];
    const float* Whh1z = &s.Whh1[gz * PW];
    const float* Whh1n = &s.Whh1[gn * PW];

    const u64 iR0 = packbias(s.bih0[gr] + s.bhh0[gr]);
    const u64 iZ0 = packbias(s.bih0[gz] + s.bhh0[gz]);
    const u64 iXN0 = packbias(s.bih0[gn]);
    const u64 iHN0 = packbias(s.bhh0[gn]);
    const u64 iR1 = packbias(s.bih1[gr] + s.bhh1[gr]);
    const u64 iZ1 = packbias(s.bih1[gz] + s.bhh1[gz]);
    const u64 iXN1 = packbias(s.bih1[gn]);
    const u64 iHN1 = packbias(s.bhh1[gn]);

    // ---- Solo layer bodies (pipeline peels only) ----
    auto layer0_solo = [&](int cur, int nxt) {
        u64 aR[NBPT], aZ[NBPT], aXN[NBPT], aHN[NBPT];
        #pragma unroll
        for (int b = 0; b < NBPT; ++b) {
            aR[b] = iR0; aZ[b] = iZ0; aXN[b] = iXN0; aHN[b] = iHN0;
        }
        #pragma unroll
        for (int kp = 0; kp < 3; ++kp) {
            F2U w0; w0.f = *(const float2*)&s.Wih0[gr * 8 + 2 * kp];
            F2U w1; w1.f = *(const float2*)&s.Wih0[gz * 8 + 2 * kp];
            F2U w2; w2.f = *(const float2*)&s.Wih0[gn * 8 + 2 * kp];
            #pragma unroll
            for (int b = 0; b < NBPT; ++b) {
                F2U xv; xv.f = *(const float2*)&s.xs[cur][bb0 + b][2 * kp];
                FFMA2(aR[b],  xv.u, w0.u);
                FFMA2(aZ[b],  xv.u, w1.u);
                FFMA2(aXN[b], xv.u, w2.u);
            }
        }
        #pragma unroll 4
        for (int kc = 0; kc < 16; ++kc) {
            const int k = kc * 4;
            F4U w0; w0.f = *(const float4*)&Whh0r[k];
            F4U w1; w1.f = *(const float4*)&Whh0z[k];
            F4U w2; w2.f = *(const float4*)&Whh0n[k];
            #pragma unroll
            for (int b = 0; b < NBPT; ++b) {
                F4U h; h.f = *(const float4*)&s.h1[cur][bb0 + b][k];
                FFMA2(aR[b],  h.u[0], w0.u[0]);
                FFMA2(aR[b],  h.u[1], w0.u[1]);
                FFMA2(aZ[b],  h.u[0], w1.u[0]);
                FFMA2(aZ[b],  h.u[1], w1.u[1]);
                FFMA2(aHN[b], h.u[0], w2.u[0]);
                FFMA2(aHN[b], h.u[1], w2.u[1]);
            }
        }
        #pragma unroll
        for (int b = 0; b < NBPT; ++b) {
            float r = sigf(hsum(aR[b]));
            float z = sigf(hsum(aZ[b]));
            float n = tanhfast(fmaf(r, hsum(aHN[b]), hsum(aXN[b])));
            float hp = s.h1[cur][bb0 + b][gg];
            s.h1[nxt][bb0 + b][gg] = fmaf(z, hp - n, n);
        }
    };

    auto layer1_solo = [&](int cur, int nxt) {
        u64 aR[NBPT], aZ[NBPT], aXN[NBPT], aHN[NBPT];
        #pragma unroll
        for (int b = 0; b < NBPT; ++b) {
            aR[b] = iR1; aZ[b] = iZ1; aXN[b] = iXN1; aHN[b] = iHN1;
        }
        #pragma unroll 4
        for (int kc = 0; kc < 16; ++kc) {
            const int k = kc * 4;
            F4U u0; u0.f = *(const float4*)&Wih1r[k];
            F4U u1; u1.f = *(const float4*)&Wih1z[k];
            F4U u2; u2.f = *(const float4*)&Wih1n[k];
            F4U v0; v0.f = *(const float4*)&Whh1r[k];
            F4U v1; v1.f = *(const float4*)&Whh1z[k];
            F4U v2; v2.f = *(const float4*)&Whh1n[k];
            #pragma unroll
            for (int b = 0; b < NBPT; ++b) {
                F4U p; p.f = *(const float4*)&s.h1[cur][bb0 + b][k];
                F4U q; q.f = *(const float4*)&s.h2[nxt][bb0 + b][k];
                FFMA2(aR[b],  p.u[0], u0.u[0]);
                FFMA2(aR[b],  p.u[1], u0.u[1]);
                FFMA2(aZ[b],  p.u[0], u1.u[0]);
                FFMA2(aZ[b],  p.u[1], u1.u[1]);
                FFMA2(aXN[b], p.u[0], u2.u[0]);
                FFMA2(aXN[b], p.u[1], u2.u[1]);
                FFMA2(aR[b],  q.u[0], v0.u[0]);
                FFMA2(aR[b],  q.u[1], v0.u[1]);
                FFMA2(aZ[b],  q.u[0], v1.u[0]);
                FFMA2(aZ[b],  q.u[1], v1.u[1]);
                FFMA2(aHN[b], q.u[0], v2.u[0]);
                FFMA2(aHN[b], q.u[1], v2.u[1]);
            }
        }
        #pragma unroll
        for (int b = 0; b < NBPT; ++b) {
            float r = sigf(hsum(aR[b]));
            float z = sigf(hsum(aZ[b]));
            float n = tanhfast(fmaf(r, hsum(aHN[b]), hsum(aXN[b])));
            float hp = s.h2[nxt][bb0 + b][gg];
            s.h2[cur][bb0 + b][gg] = fmaf(z, hp - n, n);
        }
    };

    // ---- Pipelined time loop, fused L0(t)+L1(t-1), one barrier/step ----
    {
        if (is_pref_lane) s.xs[1][lb][li] = xlane[I_DIM];   // x for t=1
        layer0_solo(0, 1);
        __syncthreads();
    }
    for (int t = 1; t < T_STEPS; ++t) {
        const int cur = t & 1, nxt = cur ^ 1;

        float xpref = 0.0f;
        const bool do_pref = is_pref_lane && (t + 1 < T_STEPS);
        if (do_pref) xpref = xlane[(size_t)(t + 1) * I_DIM];

        // Accumulators: 4 per batch per layer (r/z folded; n split for gating)
        u64 aR0[NBPT], aZ0[NBPT], aXN0[NBPT], aHN0[NBPT];
        u64 aR1[NBPT], aZ1[NBPT], aXN1[NBPT], aHN1[NBPT];
        #pragma unroll
        for (int b = 0; b < NBPT; ++b) {
            aR0[b] = iR0; aZ0[b] = iZ0; aXN0[b] = iXN0; aHN0[b] = iHN0;
            aR1[b] = iR1; aZ1[b] = iZ1; aXN1[b] = iXN1; aHN1[b] = iHN1;
        }
        // L0 input GEMV (I=6)
        #pragma unroll
        for (int kp = 0; kp < 3; ++kp) {
            F2U w0; w0.f = *(const float2*)&s.Wih0[gr * 8 + 2 * kp];
            F2U w1; w1.f = *(const float2*)&s.Wih0[gz * 8 + 2 * kp];
            F2U w2; w2.f = *(const float2*)&s.Wih0[gn * 8 + 2 * kp];
            #pragma unroll
            for (int b = 0; b < NBPT; ++b) {
                F2U xv; xv.f = *(const float2*)&s.xs[cur][bb0 + b][2 * kp];
                FFMA2(aR0[b],  xv.u, w0.u);
                FFMA2(aZ0[b],  xv.u, w1.u);
                FFMA2(aXN0[b], xv.u, w2.u);
            }
        }
        // Fused k-loop, all 9 weight rows software-pipelined one chunk ahead.
        // h = h1[cur] feeds L0 recurrent + L1 input; q = h2[nxt] feeds L1
        // recurrent. Two independent streams; weight latency hidden by the
        // cur/next double buffer.
        {
            F4U w0n, w1n, w2n, u0n, u1n, u2n, v0n, v1n, v2n;
            w0n.f = *(const float4*)&Whh0r[0];
            w1n.f = *(const float4*)&Whh0z[0];
            w2n.f = *(const float4*)&Whh0n[0];
            u0n.f = *(const float4*)&Wih1r[0];
            u1n.f = *(const float4*)&Wih1z[0];
            u2n.f = *(const float4*)&Wih1n[0];
            v0n.f = *(const float4*)&Whh1r[0];
            v1n.f = *(const float4*)&Whh1z[0];
            v2n.f = *(const float4*)&Whh1n[0];
            #pragma unroll 2
            for (int kc = 0; kc < 16; ++kc) {
                const int k = kc * 4;
                F4U w0 = w0n, w1 = w1n, w2 = w2n;
                F4U u0 = u0n, u1 = u1n, u2 = u2n;
                F4U v0 = v0n, v1 = v1n, v2 = v2n;
                if (kc < 15) {
                    w0n.f = *(const float4*)&Whh0r[k + 4];
                    w1n.f = *(const float4*)&Whh0z[k + 4];
                    w2n.f = *(const float4*)&Whh0n[k + 4];
                    u0n.f = *(const float4*)&Wih1r[k + 4];
                    u1n.f = *(const float4*)&Wih1z[k + 4];
                    u2n.f = *(const float4*)&Wih1n[k + 4];
                    v0n.f = *(const float4*)&Whh1r[k + 4];
                    v1n.f = *(const float4*)&Whh1z[k + 4];
                    v2n.f = *(const float4*)&Whh1n[k + 4];
                }
                #pragma unroll
                for (int b = 0; b < NBPT; ++b) {
                    F4U h; h.f = *(const float4*)&s.h1[cur][bb0 + b][k];
                    F4U q; q.f = *(const float4*)&s.h2[nxt][bb0 + b][k];
                    FFMA2(aR0[b],  h.u[0], w0.u[0]);
                    FFMA2(aR0[b],  h.u[1], w0.u[1]);
                    FFMA2(aZ0[b],  h.u[0], w1.u[0]);
                    FFMA2(aZ0[b],  h.u[1], w1.u[1]);
                    FFMA2(aHN0[b], h.u[0], w2.u[0]);
                    FFMA2(aHN0[b], h.u[1], w2.u[1]);
                    FFMA2(aR1[b],  h.u[0], u0.u[0]);
                    FFMA2(aR1[b],  h.u[1], u0.u[1]);
                    FFMA2(aZ1[b],  h.u[0], u1.u[0]);
                    FFMA2(aZ1[b],  h.u[1], u1.u[1]);
                    FFMA2(aXN1[b], h.u[0], u2.u[0]);
                    FFMA2(aXN1[b], h.u[1], u2.u[1]);
                    FFMA2(aR1[b],  q.u[0], v0.u[0]);
                    FFMA2(aR1[b],  q.u[1], v0.u[1]);
                    FFMA2(aZ1[b],  q.u[0], v1.u[0]);
                    FFMA2(aZ1[b],  q.u[1], v1.u[1]);
                    FFMA2(aHN1[b], q.u[0], v2.u[0]);
                    FFMA2(aHN1[b], q.u[1], v2.u[1]);
                }
            }
        }
        // L0(t) tail -> h1[nxt]
        #pragma unroll
        for (int b = 0; b < NBPT; ++b) {
            float r = sigf(hsum(aR0[b]));
            float z = sigf(hsum(aZ0[b]));
            float n = tanhfast(fmaf(r, hsum(aHN0[b]), hsum(aXN0[b])));
            float hp = s.h1[cur][bb0 + b][gg];
            s.h1[nxt][bb0 + b][gg] = fmaf(z, hp - n, n);
        }
        // L1(t-1) tail -> h2[cur]
        #pragma unroll
        for (int b = 0; b < NBPT; ++b) {
            float r = sigf(hsum(aR1[b]));
            float z = sigf(hsum(aZ1[b]));
            float n = tanhfast(fmaf(r, hsum(aHN1[b]), hsum(aXN1[b])));
            float hp = s.h2[nxt][bb0 + b][gg];
            s.h2[cur][bb0 + b][gg] = fmaf(z, hp - n, n);
        }
        if (do_pref) s.xs[nxt][lb][li] = xpref;
        __syncthreads();
    }
    // Peel: L1(255). Virtual t=256: cur=0, nxt=1.
    layer1_solo(0, 1);
    __syncthreads();

    // ---- Final FC: h2_255 is in buffer 0 ----
    if (tid < BB) {
        float acc = s.bfc;
        #pragma unroll 8
        for (int k = 0; k < HDIM; ++k)
            acc = fmaf(s.h2[0][tid][k], s.wfc[k], acc);
        out[b0 + tid] = acc;
    }
}

extern "C" void kernel_launch(void* const* d_in, const int* in_sizes, int n_in,
                              void* d_out, int out_size)
{
    const float* x     = (const float*)d_in[0];
    const float* W_ih0 = (const float*)d_in[1];
    const float* W_hh0 = (const float*)d_in[2];
    const float* b_ih0 = (const float*)d_in[3];
    const float* b_hh0 = (const float*)d_in[4];
    const float* W_ih1 = (const float*)d_in[5];
    const float* W_hh1 = (const float*)d_in[6];
    const float* b_ih1 = (const float*)d_in[7];
    const float* b_hh1 = (const float*)d_in[8];
    const float* W_fc  = (const float*)d_in[9];
    const float* b_fc  = (const float*)d_in[10];
    float* out = (float*)d_out;

    (void)in_sizes; (void)n_in; (void)out_size;

    static_assert(sizeof(SmemLayout) < 227 * 1024, "smem over budget");
    cudaFuncSetAttribute(gru_fused_kernel,
                         cudaFuncAttributeMaxDynamicSharedMemorySize,
                         (int)sizeof(SmemLayout));

    gru_fused_kernel<<<NCTA, NT, sizeof(SmemLayout)>>>(
        x, W_ih0, W_hh0, b_ih0, b_hh0,
        W_ih1, W_hh1, b_ih1, b_hh1,
        W_fc, b_fc, out);
}

// round 14
// speedup vs baseline: 1.5473x; 1.5473x over previous
#include <cuda_runtime.h>
#include <cuda_bf16.h>
#include <cstdint>

// B=4096, T=256, I=6, H=64, gates=3H=192, 2 GRU layers + FC(H->1)
#define T_STEPS 256
#define I_DIM   6
#define HDIM    64
#define G3      192
#define BB      32
#define NT      256
#define NBPT    8
#define NCTA    128

#define WROW 144                 // bytes per row: 72 bf16 (64 used + pad)
#define WT   (G3 * WROW)         // 27648 B per weight tile
#define HT   (BB * WROW)         // 4608 B per h tile

// ---------------- SMEM layout (byte offsets) ----------------
#define SM_W0HI  0
#define SM_W0LO  (SM_W0HI + WT)
#define SM_W1IHI (SM_W0LO + WT)
#define SM_W1ILO (SM_W1IHI + WT)
#define SM_W1HHI (SM_W1ILO + WT)
#define SM_W1HLO (SM_W1HHI + WT)
#define SM_H1HI  (SM_W1HLO + WT)     // 165888
#define SM_H1LO  (SM_H1HI + HT)
#define SM_H2HI  (SM_H1LO + HT)
#define SM_H2LO  (SM_H2HI + HT)
#define SM_WIH0  (SM_H2LO + HT)      // f32 [192][9]
#define SM_BIAS  (SM_WIH0 + G3 * 9 * 4)
#define SM_XS    (SM_BIAS + 4 * G3 * 4)   // [2][32][8] f32
#define SM_WFC   (SM_XS + 2 * BB * 8 * 4)
#define SM_BFC   (SM_WFC + HDIM * 4)
#define SM_EXA   (((SM_BFC + 4) + 127) & ~127)  // [128][33] f32
#define SM_EXN   (SM_EXA + 128 * 33 * 4)        // [64][33]
#define SM_EXX   (SM_EXN + 64 * 33 * 4)         // [64][33]
#define SM_TOTAL (SM_EXX + 64 * 33 * 4 + 128)
static_assert(SM_TOTAL < 227 * 1024, "smem over budget");

__device__ __forceinline__ uint32_t smem_u32(const void* p) {
    uint32_t a;
    asm("{ .reg .u64 t; cvta.to.shared.u64 t, %1; cvt.u32.u64 %0, t; }"
        : "=r"(a) : "l"(p));
    return a;
}
__device__ __forceinline__ void ldsm4(uint32_t addr, uint32_t r[4]) {
    asm volatile("ldmatrix.sync.aligned.m8n8.x4.shared.b16 {%0,%1,%2,%3}, [%4];"
                 : "=r"(r[0]), "=r"(r[1]), "=r"(r[2]), "=r"(r[3]) : "r"(addr));
}
__device__ __forceinline__ void mma16816(float d[4], const uint32_t a[4],
                                         const uint32_t b[2]) {
    asm volatile(
        "mma.sync.aligned.m16n8k16.row.col.f32.bf16.bf16.f32 "
        "{%0,%1,%2,%3}, {%4,%5,%6,%7}, {%8,%9}, {%0,%1,%2,%3};"
        : "+f"(d[0]), "+f"(d[1]), "+f"(d[2]), "+f"(d[3])
        : "r"(a[0]), "r"(a[1]), "r"(a[2]), "r"(a[3]), "r"(b[0]), "r"(b[1]));
}
__device__ __forceinline__ float sigf(float v) {
    return __fdividef(1.0f, 1.0f + __expf(-v));
}
__device__ __forceinline__ float tanhfast(float v) {
    float c = fminf(fmaxf(v, -15.0f), 15.0f);
    float e = __expf(2.0f * c);
    return __fdividef(e - 1.0f, e + 1.0f);
}
__device__ __forceinline__ void split_store(char* base, float h) {
    __nv_bfloat16 hi = __float2bfloat16(h);
    float hif = __bfloat162float(hi);
    __nv_bfloat16 lo = __float2bfloat16(h - hif);
    *(__nv_bfloat16*)(base) = hi;
    *(__nv_bfloat16*)(base + HT) = lo;   // LO tile sits HT after HI tile
}

__global__ __launch_bounds__(NT) void gru_mma_kernel(
    const float* __restrict__ x,
    const float* __restrict__ W_ih0, const float* __restrict__ W_hh0,
    const float* __restrict__ b_ih0, const float* __restrict__ b_hh0,
    const float* __restrict__ W_ih1, const float* __restrict__ W_hh1,
    const float* __restrict__ b_ih1, const float* __restrict__ b_hh1,
    const float* __restrict__ W_fc,  const float* __restrict__ b_fc,
    float* __restrict__ out)
{
    extern __shared__ char smem[];
    const uint32_t sb = smem_u32(smem);
    const int tid = threadIdx.x;
    const int lane = tid & 31, wid = tid >> 5;
    const int b0 = blockIdx.x * BB;

    // ---- Stage weights: fp32 -> bf16 hi/lo row-major tiles ----
    for (int i = tid; i < G3 * HDIM; i += NT) {
        int r = i >> 6, c = i & 63;
        int off = r * WROW + c * 2;
        {
            float w = W_hh0[i];
            __nv_bfloat16 hi = __float2bfloat16(w);
            __nv_bfloat16 lo = __float2bfloat16(w - __bfloat162float(hi));
            *(__nv_bfloat16*)(smem + SM_W0HI + off) = hi;
            *(__nv_bfloat16*)(smem + SM_W0LO + off) = lo;
        }
        {
            float w = W_ih1[i];
            __nv_bfloat16 hi = __float2bfloat16(w);
            __nv_bfloat16 lo = __float2bfloat16(w - __bfloat162float(hi));
            *(__nv_bfloat16*)(smem + SM_W1IHI + off) = hi;
            *(__nv_bfloat16*)(smem + SM_W1ILO + off) = lo;
        }
        {
            float w = W_hh1[i];
            __nv_bfloat16 hi = __float2bfloat16(w);
            __nv_bfloat16 lo = __float2bfloat16(w - __bfloat162float(hi));
            *(__nv_bfloat16*)(smem + SM_W1HHI + off) = hi;
            *(__nv_bfloat16*)(smem + SM_W1HLO + off) = lo;
        }
    }
    float* wih0 = (float*)(smem + SM_WIH0);
    for (int i = tid; i < G3 * I_DIM; i += NT)
        wih0[(i / I_DIM) * 9 + (i % I_DIM)] = W_ih0[i];
    float* bias = (float*)(smem + SM_BIAS);
    for (int i = tid; i < G3; i += NT) {
        bias[i]          = b_ih0[i];
        bias[G3 + i]     = b_hh0[i];
        bias[2 * G3 + i] = b_ih1[i];
        bias[3 * G3 + i] = b_hh1[i];
    }
    // zero all 4 h tiles (h=0 at t=0)
    for (int i = tid; i < 4 * HT / 4; i += NT)
        ((uint32_t*)(smem + SM_H1HI))[i] = 0u;
    float* xsp = (float*)(smem + SM_XS);
    if (tid < HDIM) ((float*)(smem + SM_WFC))[tid] = W_fc[tid];
    if (tid == 0) *(float*)(smem + SM_BFC) = b_fc[0];

    const bool is_pref = (tid < BB * I_DIM);
    const int lb = is_pref ? (tid / I_DIM) : 0;
    const int li = is_pref ? (tid % I_DIM) : 0;
    const float* xlane = x + (size_t)(b0 + lb) * T_STEPS * I_DIM + li;
    if (is_pref) xsp[lb * 8 + li] = xlane[0];
    __syncthreads();

    // ---- MMA decomposition ----
    // 24 units (12 m16-tiles x 2 n16-halves); warp w: nh = w>>2,
    // m-tiles {3*(w&3) .. +2}. B frags shared across the warp's 3 m-tiles.
    const int nh = wid >> 2;
    const int mtbase = 3 * (wid & 3);
    const uint32_t aOff = (uint32_t)((lane & 15) * WROW + (((lane >> 4) << 3) << 1));
    const uint32_t bOff = (uint32_t)(((((lane >> 4) << 3) + (lane & 7)) * WROW) +
                                     (((lane >> 3) & 1) << 4));
    const uint32_t bNH = (uint32_t)(nh * 16 * WROW);
    // D fragment lane mapping
    const int rb = lane >> 2;
    const int cb = nh * 16 + 2 * (lane & 3);

    // ---- Activation mapping (unchanged from fp32 kernels) ----
    const int gg = tid & 63;
    const int bg = tid >> 6;
    const int bb0 = bg * NBPT;
    const float brC0 = bias[gg] + bias[G3 + gg];
    const float bzC0 = bias[gg + 64] + bias[G3 + gg + 64];
    const float bxn0 = bias[gg + 128];
    const float bhn0 = bias[G3 + gg + 128];
    const float br1  = bias[2 * G3 + gg] + bias[3 * G3 + gg];
    const float bz1  = bias[2 * G3 + gg + 64] + bias[3 * G3 + gg + 64];
    const float bxn1 = bias[2 * G3 + gg + 128];
    const float bhn1 = bias[3 * G3 + gg + 128];

    float h1reg[NBPT], h2reg[NBPT];
    #pragma unroll
    for (int b = 0; b < NBPT; ++b) { h1reg[b] = 0.0f; h2reg[b] = 0.0f; }

    float* exA = (float*)(smem + SM_EXA);
    float* exN = (float*)(smem + SM_EXN);
    float* exX = (float*)(smem + SM_EXX);

    for (int t = 0; t < T_STEPS; ++t) {
        const int cur = t & 1, nxt = cur ^ 1;
        const float* xcur = xsp + cur * BB * 8;

        // ======== Phase 1: L0 MMA  D0 = Whh0 (x) H1_old ========
        float acc[3][2][4];
        #pragma unroll
        for (int j = 0; j < 3; ++j)
            #pragma unroll
            for (int tt = 0; tt < 2; ++tt)
                #pragma unroll
                for (int e = 0; e < 4; ++e) acc[j][tt][e] = 0.0f;
        #pragma unroll
        for (int kt = 0; kt < 4; ++kt) {
            uint32_t bh[4], bl[4];
            ldsm4(sb + SM_H1HI + bNH + kt * 32 + bOff, bh);
            ldsm4(sb + SM_H1LO + bNH + kt * 32 + bOff, bl);
            #pragma unroll
            for (int j = 0; j < 3; ++j) {
                uint32_t wa = (uint32_t)((mtbase + j) * 16 * WROW + kt * 32) + aOff;
                uint32_t ah[4], al[4];
                ldsm4(sb + SM_W0HI + wa, ah);
                ldsm4(sb + SM_W0LO + wa, al);
                mma16816(acc[j][0], ah, &bh[0]);
                mma16816(acc[j][1], ah, &bh[2]);
                mma16816(acc[j][0], ah, &bl[0]);
                mma16816(acc[j][1], ah, &bl[2]);
                mma16816(acc[j][0], al, &bh[0]);
                mma16816(acc[j][1], al, &bh[2]);
            }
        }
        // x-side GEMV (fp32, I=6) — independent work mixed in
        float xr[NBPT], xz[NBPT], xn[NBPT];
        #pragma unroll
        for (int b = 0; b < NBPT; ++b) { xr[b] = brC0; xz[b] = bzC0; xn[b] = bxn0; }
        #pragma unroll
        for (int k = 0; k < I_DIM; ++k) {
            float wr = wih0[gg * 9 + k], wz = wih0[(gg + 64) * 9 + k],
                  wn = wih0[(gg + 128) * 9 + k];
            #pragma unroll
            for (int b = 0; b < NBPT; ++b) {
                float xv = xcur[(bb0 + b) * 8 + k];
                xr[b] = fmaf(xv, wr, xr[b]);
                xz[b] = fmaf(xv, wz, xz[b]);
                xn[b] = fmaf(xv, wn, xn[b]);
            }
        }
        float xpref = 0.0f;
        const bool do_pref = is_pref && (t + 1 < T_STEPS);
        if (do_pref) xpref = xlane[(size_t)(t + 1) * I_DIM];

        // store D0 frags: rows 0-127 -> exA, rows 128-191 -> exN
        #pragma unroll
        for (int j = 0; j < 3; ++j) {
            int mt = mtbase + j;
            float* dst = (mt < 8) ? exA : exN;
            int r0 = ((mt < 8) ? mt : mt - 8) * 16 + rb;
            #pragma unroll
            for (int tt = 0; tt < 2; ++tt) {
                int c = cb + tt * 8;
                dst[r0 * 33 + c]           = acc[j][tt][0];
                dst[r0 * 33 + c + 1]       = acc[j][tt][1];
                dst[(r0 + 8) * 33 + c]     = acc[j][tt][2];
                dst[(r0 + 8) * 33 + c + 1] = acc[j][tt][3];
            }
        }
        __syncthreads();

        // ======== Phase 2: L0 activations -> h1_new ========
        #pragma unroll
        for (int b = 0; b < NBPT; ++b) {
            int bb = bb0 + b;
            float r = sigf(xr[b] + exA[gg * 33 + bb]);
            float z = sigf(xz[b] + exA[(gg + 64) * 33 + bb]);
            float n = tanhfast(fmaf(r, exN[gg * 33 + bb] + bhn0, xn[b]));
            float h = fmaf(z, h1reg[b] - n, n);
            h1reg[b] = h;
            split_store(smem + SM_H1HI + bb * WROW + gg * 2, h);
        }
        __syncthreads();

        // ======== Phase 3: L1 MMA  D1x = Wih1(x)H1_new, D1h = Whh1(x)H2_old
        float accX[3][2][4], accH[3][2][4];
        #pragma unroll
        for (int j = 0; j < 3; ++j)
            #pragma unroll
            for (int tt = 0; tt < 2; ++tt)
                #pragma unroll
                for (int e = 0; e < 4; ++e) { accX[j][tt][e] = 0.0f; accH[j][tt][e] = 0.0f; }
        #pragma unroll
        for (int kt = 0; kt < 4; ++kt) {
            uint32_t ph[4], pl[4], qh[4], ql[4];
            ldsm4(sb + SM_H1HI + bNH + kt * 32 + bOff, ph);
            ldsm4(sb + SM_H1LO + bNH + kt * 32 + bOff, pl);
            ldsm4(sb + SM_H2HI + bNH + kt * 32 + bOff, qh);
            ldsm4(sb + SM_H2LO + bNH + kt * 32 + bOff, ql);
            #pragma unroll
            for (int j = 0; j < 3; ++j) {
                uint32_t wa = (uint32_t)((mtbase + j) * 16 * WROW + kt * 32) + aOff;
                uint32_t ah[4], al[4];
                ldsm4(sb + SM_W1IHI + wa, ah);
                ldsm4(sb + SM_W1ILO + wa, al);
                mma16816(accX[j][0], ah, &ph[0]);
                mma16816(accX[j][1], ah, &ph[2]);
                mma16816(accX[j][0], ah, &pl[0]);
                mma16816(accX[j][1], ah, &pl[2]);
                mma16816(accX[j][0], al, &ph[0]);
                mma16816(accX[j][1], al, &ph[2]);
                ldsm4(sb + SM_W1HHI + wa, ah);
                ldsm4(sb + SM_W1HLO + wa, al);
                mma16816(accH[j][0], ah, &qh[0]);
                mma16816(accH[j][1], ah, &qh[2]);
                mma16816(accH[j][0], ah, &ql[0]);
                mma16816(accH[j][1], ah, &ql[2]);
                mma16816(accH[j][0], al, &qh[0]);
                mma16816(accH[j][1], al, &qh[2]);
            }
        }
        // store: rows<128 -> exA (x+h summed); rows>=128 -> exN (h), exX (x)
        #pragma unroll
        for (int j = 0; j < 3; ++j) {
            int mt = mtbase + j;
            if (mt < 8) {
                int r0 = mt * 16 + rb;
                #pragma unroll
                for (int tt = 0; tt < 2; ++tt) {
                    int c = cb + tt * 8;
                    exA[r0 * 33 + c]           = accX[j][tt][0] + accH[j][tt][0];
                    exA[r0 * 33 + c + 1]       = accX[j][tt][1] + accH[j][tt][1];
                    exA[(r0 + 8) * 33 + c]     = accX[j][tt][2] + accH[j][tt][2];
                    exA[(r0 + 8) * 33 + c + 1] = accX[j][tt][3] + accH[j][tt][3];
                }
            } else {
                int r0 = (mt - 8) * 16 + rb;
                #pragma unroll
                for (int tt = 0; tt < 2; ++tt) {
                    int c = cb + tt * 8;
                    exN[r0 * 33 + c]           = accH[j][tt][0];
                    exN[r0 * 33 + c + 1]       = accH[j][tt][1];
                    exN[(r0 + 8) * 33 + c]     = accH[j][tt][2];
                    exN[(r0 + 8) * 33 + c + 1] = accH[j][tt][3];
                    exX[r0 * 33 + c]           = accX[j][tt][0];
                    exX[r0 * 33 + c + 1]       = accX[j][tt][1];
                    exX[(r0 + 8) * 33 + c]     = accX[j][tt][2];
                    exX[(r0 + 8) * 33 + c + 1] = accX[j][tt][3];
                }
            }
        }
        __syncthreads();

        // ======== Phase 4: L1 activations -> h2_new ========
        #pragma unroll
        for (int b = 0; b < NBPT; ++b) {
            int bb = bb0 + b;
            float r = sigf(exA[gg * 33 + bb] + br1);
            float z = sigf(exA[(gg + 64) * 33 + bb] + bz1);
            float n = tanhfast(fmaf(r, exN[gg * 33 + bb] + bhn1,
                                    exX[gg * 33 + bb] + bxn1));
            float h = fmaf(z, h2reg[b] - n, n);
            h2reg[b] = h;
            split_store(smem + SM_H2HI + bb * WROW + gg * 2, h);
        }
        if (do_pref) xsp[nxt * BB * 8 + lb * 8 + li] = xpref;
        __syncthreads();
    }

    // ---- Final FC: out[b] = h2 . wfc + bfc (h2reg exchange via exA) ----
    #pragma unroll
    for (int b = 0; b < NBPT; ++b) exA[(bb0 + b) * 68 + gg] = h2reg[b];
    __syncthreads();
    if (tid < BB) {
        const float* wfc = (const float*)(smem + SM_WFC);
        float acc2 = *(const float*)(smem + SM_BFC);
        #pragma unroll 8
        for (int k = 0; k < HDIM; ++k)
            acc2 = fmaf(exA[tid * 68 + k], wfc[k], acc2);
        out[b0 + tid] = acc2;
    }
}

extern "C" void kernel_launch(void* const* d_in, const int* in_sizes, int n_in,
                              void* d_out, int out_size)
{
    const float* x     = (const float*)d_in[0];
    const float* W_ih0 = (const float*)d_in[1];
    const float* W_hh0 = (const float*)d_in[2];
    const float* b_ih0 = (const float*)d_in[3];
    const float* b_hh0 = (const float*)d_in[4];
    const float* W_ih1 = (const float*)d_in[5];
    const float* W_hh1 = (const float*)d_in[6];
    const float* b_ih1 = (const float*)d_in[7];
    const float* b_hh1 = (const float*)d_in[8];
    const float* W_fc  = (const float*)d_in[9];
    const float* b_fc  = (const float*)d_in[10];
    float* out = (float*)d_out;
    (void)in_sizes; (void)n_in; (void)out_size;

    cudaFuncSetAttribute(gru_mma_kernel,
                         cudaFuncAttributeMaxDynamicSharedMemorySize, SM_TOTAL);
    gru_mma_kernel<<<NCTA, NT, SM_TOTAL>>>(
        x, W_ih0, W_hh0, b_ih0, b_hh0,
        W_ih1, W_hh1, b_ih1, b_hh1,
        W_fc, b_fc, out);
}